// round 1
// baseline (speedup 1.0000x reference)
#include <cuda_runtime.h>

#define HID   1024
#define TS1   1001          // TYPE_SIZE + 1 embedding rows
#define BATCH 32
#define SEQ   512
#define NTOK  (BATCH * SEQ) // 16384 tokens
#define NG    5             // gates actually used: gi, gz, go, gib, gd
#define NP    (NG * HID)    // 5120 preact columns per embedding row
#define WROW  2048          // W_rec row stride (2H), we use first HID cols

// Device-global scratch (no allocations allowed in kernel_launch)
__device__ float g_preact[TS1 * NP];       // ~20.5 MB: raw dot products
__device__ float g_table [TS1 * 4 * HID];  // ~16.4 MB: {c, c_bar, sig(go), softplus(gd)}

// chunk index within the 7H gate vector for each of our 5 used gates
__constant__ int c_chunk[NG] = {0, 2, 3, 4, 6};  // gi, gz, go, gib, gd

// ---------------------------------------------------------------------------
// Kernel 1: C[e, n] = sum_k emb[e,k] * W_rec[row(n), k]
//   n = c*HID + h, row(n) = c_chunk[c]*HID + h
// 128x128 block tile, 8x8 per thread, BK=16, fp32 SIMT.
// ---------------------------------------------------------------------------
#define BM 128
#define BN 128
#define BK 16
#define TM 8
#define TN 8

__global__ __launch_bounds__(256)
void gemm_kernel(const float* __restrict__ emb, const float* __restrict__ W) {
    __shared__ float As[BK][BM + 4];
    __shared__ float Bs[BK][BN + 4];

    const int bm = blockIdx.y * BM;           // embedding-row tile
    const int bn = blockIdx.x * BN;           // gate-column tile (within NP)
    const int chunk = bn / HID;               // 128 | 1024, so constant per block
    const int wbase = c_chunk[chunk] * HID + (bn % HID);  // W_rec row base

    const int tid = threadIdx.x;
    const int tx  = tid & 15;                 // 0..15 -> n
    const int ty  = tid >> 4;                 // 0..15 -> m

    float acc[TM][TN];
#pragma unroll
    for (int i = 0; i < TM; i++)
#pragma unroll
        for (int j = 0; j < TN; j++) acc[i][j] = 0.f;

    for (int k0 = 0; k0 < HID; k0 += BK) {
        // ---- load A tile (128 rows x 16 k), transposed into As[k][m]
#pragma unroll
        for (int p = 0; p < 2; p++) {
            int idx = p * 256 + tid;
            int row = idx >> 2;               // 0..127
            int kl  = (idx & 3) * 4;          // 0,4,8,12
            int e   = bm + row;
            float4 v = make_float4(0.f, 0.f, 0.f, 0.f);
            if (e < TS1)
                v = *reinterpret_cast<const float4*>(emb + e * HID + k0 + kl);
            As[kl + 0][row] = v.x;
            As[kl + 1][row] = v.y;
            As[kl + 2][row] = v.z;
            As[kl + 3][row] = v.w;
        }
        // ---- load B tile (128 n x 16 k), transposed into Bs[k][n]
#pragma unroll
        for (int p = 0; p < 2; p++) {
            int idx = p * 256 + tid;
            int row = idx >> 2;               // n_local 0..127
            int kl  = (idx & 3) * 4;
            float4 v = *reinterpret_cast<const float4*>(
                W + (size_t)(wbase + row) * WROW + k0 + kl);
            Bs[kl + 0][row] = v.x;
            Bs[kl + 1][row] = v.y;
            Bs[kl + 2][row] = v.z;
            Bs[kl + 3][row] = v.w;
        }
        __syncthreads();

#pragma unroll
        for (int k = 0; k < BK; k++) {
            float a[TM], b[TN];
#pragma unroll
            for (int i = 0; i < TM; i++) a[i] = As[k][ty * TM + i];
#pragma unroll
            for (int j = 0; j < TN; j++) b[j] = Bs[k][tx * TN + j];
#pragma unroll
            for (int i = 0; i < TM; i++)
#pragma unroll
                for (int j = 0; j < TN; j++)
                    acc[i][j] += a[i] * b[j];
        }
        __syncthreads();
    }

    // ---- store
#pragma unroll
    for (int i = 0; i < TM; i++) {
        int e = bm + ty * TM + i;
        if (e < TS1) {
            float* dst = g_preact + (size_t)e * NP + bn + tx * TN;
#pragma unroll
            for (int j = 0; j < TN; j += 4) {
                float4 v = make_float4(acc[i][j], acc[i][j+1], acc[i][j+2], acc[i][j+3]);
                *reinterpret_cast<float4*>(dst + j) = v;
            }
        }
    }
}

// ---------------------------------------------------------------------------
// Kernel 2: add bias, apply activations, build per-embedding table
//   table[e, 0, h] = sigmoid(gi)*tanh(gz)   (= c)
//   table[e, 1, h] = sigmoid(gib)*tanh(gz)  (= c_bar)
//   table[e, 2, h] = sigmoid(go)
//   table[e, 3, h] = softplus(gd)
// ---------------------------------------------------------------------------
__device__ __forceinline__ float sigmoidf_(float x) {
    return 1.f / (1.f + expf(-x));
}

__global__ __launch_bounds__(256)
void act_kernel(const float* __restrict__ brec) {
    int idx = blockIdx.x * blockDim.x + threadIdx.x;
    if (idx >= TS1 * HID) return;
    int e = idx / HID;
    int h = idx - e * HID;
    const float* P = g_preact + (size_t)e * NP;

    float gi  = P[0 * HID + h] + brec[0 * HID + h];
    float gz  = P[1 * HID + h] + brec[2 * HID + h];
    float go  = P[2 * HID + h] + brec[3 * HID + h];
    float gib = P[3 * HID + h] + brec[4 * HID + h];
    float gd  = P[4 * HID + h] + brec[6 * HID + h];

    float tz  = tanhf(gz);
    float cc  = sigmoidf_(gi)  * tz;
    float cb  = sigmoidf_(gib) * tz;
    float goa = sigmoidf_(go);
    float gda = fmaxf(gd, 0.f) + log1pf(expf(-fabsf(gd)));  // stable softplus

    float* T = g_table + (size_t)e * (4 * HID);
    T[0 * HID + h] = cc;
    T[1 * HID + h] = cb;
    T[2 * HID + h] = goa;
    T[3 * HID + h] = gda;
}

// ---------------------------------------------------------------------------
// Kernel 3: per-token gather + decay + write 5 outputs
//   out shape [5, T, B, H]; block = one token (t,b); 256 threads x float4
// ---------------------------------------------------------------------------
__global__ __launch_bounds__(256)
void token_kernel(const int* __restrict__ ev, const float* __restrict__ dur,
                  float* __restrict__ out) {
    const int tok = blockIdx.x;        // = t*BATCH + b (matches output layout)
    const int t = tok >> 5;            // /32
    const int b = tok & 31;

    const int   e = ev[b * SEQ + t];   // inputs are [B, T]
    const float d = dur[b * SEQ + t];

    const float* T = g_table + (size_t)e * (4 * HID);
    const int h = threadIdx.x * 4;

    float4 c  = *reinterpret_cast<const float4*>(T + 0 * HID + h);
    float4 cb = *reinterpret_cast<const float4*>(T + 1 * HID + h);
    float4 go = *reinterpret_cast<const float4*>(T + 2 * HID + h);
    float4 gd = *reinterpret_cast<const float4*>(T + 3 * HID + h);

    float4 hd;
    hd.x = go.x * tanhf(cb.x + (c.x - cb.x) * expf(-gd.x * d));
    hd.y = go.y * tanhf(cb.y + (c.y - cb.y) * expf(-gd.y * d));
    hd.z = go.z * tanhf(cb.z + (c.z - cb.z) * expf(-gd.z * d));
    hd.w = go.w * tanhf(cb.w + (c.w - cb.w) * expf(-gd.w * d));

    const size_t stride = (size_t)SEQ * BATCH * HID;     // one [T,B,H] slab
    const size_t base   = (size_t)tok * HID + h;

    *reinterpret_cast<float4*>(out + 0 * stride + base) = hd;
    *reinterpret_cast<float4*>(out + 1 * stride + base) = c;
    *reinterpret_cast<float4*>(out + 2 * stride + base) = cb;
    *reinterpret_cast<float4*>(out + 3 * stride + base) = go;
    *reinterpret_cast<float4*>(out + 4 * stride + base) = gd;
}

// ---------------------------------------------------------------------------
extern "C" void kernel_launch(void* const* d_in, const int* in_sizes, int n_in,
                              void* d_out, int out_size) {
    const int*   ev  = (const int*)  d_in[0];   // event_seqs   [32, 512] int32
    const float* dur = (const float*)d_in[1];   // duration_seqs[32, 512]
    const float* emb = (const float*)d_in[2];   // emb_table [1001, 1024]
    const float* W   = (const float*)d_in[3];   // W_rec [7168, 2048]
    const float* br  = (const float*)d_in[4];   // b_rec [7168]
    float* out = (float*)d_out;                 // [5, 512, 32, 1024]

    dim3 g1(NP / BN, (TS1 + BM - 1) / BM);      // (40, 8)
    gemm_kernel<<<g1, 256>>>(emb, W);

    act_kernel<<<(TS1 * HID + 255) / 256, 256>>>(br);

    token_kernel<<<NTOK, 256>>>(ev, dur, out);
}

// round 3
// speedup vs baseline: 1.7877x; 1.7877x over previous
#include <cuda_runtime.h>
#include <cuda_bf16.h>
#include <cstdint>

#define HID   1024
#define TS1   1001            // TYPE_SIZE + 1 embedding rows
#define MPAD  1024            // padded M (8 tiles of 128)
#define BATCH 32
#define SEQ   512
#define NTOK  (BATCH * SEQ)
#define NG    5               // used gates: gi, gz, go, gib, gd
#define NP    (NG * HID)      // 5120
#define WROW  2048            // W_rec row stride (2H)
#define KK    3072            // K' = 3 * HID  (hi*hi | lo*hi | hi*lo)

// ---------------- device-global scratch (no allocs allowed) ----------------
__device__ __nv_bfloat16 g_A[MPAD * KK];     // 6 MB   A' = [hi | lo | hi]
__device__ __nv_bfloat16 g_B[NP * KK];       // 30 MB  B' = [hi | hi | lo]
__device__ float g_preact[TS1 * NP];         // 20.5 MB
__device__ float g_table [TS1 * 4 * HID];    // 16.4 MB

__constant__ int c_chunk[NG] = {0, 2, 3, 4, 6};   // gi, gz, go, gib, gd

// ---------------- base-target PTX helpers (no 'a'-gated instrs!) ----------
__device__ __forceinline__ uint32_t smem_u32(const void* p) {
    uint32_t a;
    asm("{ .reg .u64 t; cvta.to.shared.u64 t, %1; cvt.u32.u64 %0, t; }"
        : "=r"(a) : "l"(p));
    return a;
}
#define CP_ASYNC16(dst, src) \
    asm volatile("cp.async.cg.shared.global [%0], [%1], 16;" \
                 :: "r"(dst), "l"(src))
#define CP_COMMIT() asm volatile("cp.async.commit_group;" ::: "memory")
#define CP_WAIT0()  asm volatile("cp.async.wait_group 0;" ::: "memory")
#define CP_WAIT1()  asm volatile("cp.async.wait_group 1;" ::: "memory")

__device__ __forceinline__ void ldsm_x4(uint32_t* r, uint32_t addr) {
    asm volatile("ldmatrix.sync.aligned.m8n8.x4.shared.b16 {%0,%1,%2,%3}, [%4];"
        : "=r"(r[0]), "=r"(r[1]), "=r"(r[2]), "=r"(r[3]) : "r"(addr));
}
__device__ __forceinline__ void ldsm_x2(uint32_t* r, uint32_t addr) {
    asm volatile("ldmatrix.sync.aligned.m8n8.x2.shared.b16 {%0,%1}, [%2];"
        : "=r"(r[0]), "=r"(r[1]) : "r"(addr));
}
__device__ __forceinline__ void mma_bf16(float* c, const uint32_t* a,
                                         const uint32_t* b) {
    asm volatile(
        "mma.sync.aligned.m16n8k16.row.col.f32.bf16.bf16.f32 "
        "{%0,%1,%2,%3}, {%4,%5,%6,%7}, {%8,%9}, {%0,%1,%2,%3};"
        : "+f"(c[0]), "+f"(c[1]), "+f"(c[2]), "+f"(c[3])
        : "r"(a[0]), "r"(a[1]), "r"(a[2]), "r"(a[3]), "r"(b[0]), "r"(b[1]));
}

// ---------------------------------------------------------------------------
// Kernel 0a/0b: fp32 -> bf16 hi/lo split, packed along K'
//   A'[e, k]      = hi,  A'[e, 1024+k] = lo,  A'[e, 2048+k] = hi
//   B'[n, k]      = hi,  B'[n, 1024+k] = hi,  B'[n, 2048+k] = lo
// ---------------------------------------------------------------------------
__global__ __launch_bounds__(256)
void conv_A(const float* __restrict__ emb) {
    int idx = blockIdx.x * 256 + threadIdx.x;       // over MPAD*HID
    if (idx >= MPAD * HID) return;
    int e = idx >> 10, k = idx & 1023;
    float a = (e < TS1) ? emb[idx] : 0.f;
    __nv_bfloat16 hi = __float2bfloat16(a);
    __nv_bfloat16 lo = __float2bfloat16(a - __bfloat162float(hi));
    __nv_bfloat16* dst = g_A + (size_t)e * KK + k;
    dst[0]    = hi;
    dst[1024] = lo;
    dst[2048] = hi;
}

__global__ __launch_bounds__(256)
void conv_B(const float* __restrict__ W) {
    int idx = blockIdx.x * 256 + threadIdx.x;       // over NP*HID
    if (idx >= NP * HID) return;
    int n = idx >> 10, k = idx & 1023;
    int c = n >> 10, h = n & 1023;
    float a = W[(size_t)(c_chunk[c] * HID + h) * WROW + k];
    __nv_bfloat16 hi = __float2bfloat16(a);
    __nv_bfloat16 lo = __float2bfloat16(a - __bfloat162float(hi));
    __nv_bfloat16* dst = g_B + (size_t)n * KK + k;
    dst[0]    = hi;
    dst[1024] = hi;
    dst[2048] = lo;
}

// ---------------------------------------------------------------------------
// Kernel 1: bf16 mma.sync GEMM.  preact[e, n] = sum_k' A'[e,k'] * B'[n,k']
// 128x128 block, BK=32, double-buffered cp.async, 8 warps (2x4), 64x32/warp.
// SMEM row stride 40 bf16 (80 B): conflict-free LDSM for 8 consecutive rows.
// ---------------------------------------------------------------------------
#define BK     32
#define LDS_S  40                         // smem row stride in bf16 elements
#define KT     (KK / BK)                  // 96
#define STG_E  (128 * LDS_S)              // elements per stage

__global__ __launch_bounds__(256)
void gemm_hmma() {
    __shared__ __align__(16) __nv_bfloat16 As[2][STG_E];
    __shared__ __align__(16) __nv_bfloat16 Bs[2][STG_E];

    const int tid = threadIdx.x;
    const int wid = tid >> 5, lane = tid & 31;
    const int bm = blockIdx.y * 128;
    const int bn = blockIdx.x * 128;
    const int wm = (wid >> 2) * 64;        // warp m offset (0 | 64)
    const int wn = (wid & 3) * 32;         // warp n offset (0..96)

    const __nv_bfloat16* gA = g_A + (size_t)bm * KK;
    const __nv_bfloat16* gB = g_B + (size_t)bn * KK;

    // per-thread load slots: 2 chunks of 16B per matrix per stage
    const int r0 = tid >> 2, g0 = tid & 3;             // chunk tid
    const int r1 = (tid + 256) >> 2, g1 = tid & 3;     // chunk tid+256

    auto issue = [&](int kt, int s) {
        const int k0 = kt * BK;
        uint32_t dA = smem_u32(&As[s][0]);
        uint32_t dB = smem_u32(&Bs[s][0]);
        CP_ASYNC16(dA + r0 * 80 + g0 * 16, gA + (size_t)r0 * KK + k0 + g0 * 8);
        CP_ASYNC16(dA + r1 * 80 + g1 * 16, gA + (size_t)r1 * KK + k0 + g1 * 8);
        CP_ASYNC16(dB + r0 * 80 + g0 * 16, gB + (size_t)r0 * KK + k0 + g0 * 8);
        CP_ASYNC16(dB + r1 * 80 + g1 * 16, gB + (size_t)r1 * KK + k0 + g1 * 8);
    };

    float acc[4][4][4];                    // [m-frag][n-frag][4]
#pragma unroll
    for (int i = 0; i < 4; i++)
#pragma unroll
        for (int j = 0; j < 4; j++)
#pragma unroll
            for (int v = 0; v < 4; v++) acc[i][j][v] = 0.f;

    issue(0, 0);
    CP_COMMIT();

    for (int kt = 0; kt < KT; kt++) {
        const int s = kt & 1;
        if (kt + 1 < KT) {
            issue(kt + 1, s ^ 1);
            CP_COMMIT();
            CP_WAIT1();
        } else {
            CP_WAIT0();
        }
        __syncthreads();

        const uint32_t aBase = smem_u32(&As[s][0]);
        const uint32_t bBase = smem_u32(&Bs[s][0]);
#pragma unroll
        for (int ks = 0; ks < 2; ks++) {
            uint32_t af[4][4], bf[4][2];
            // A frags: rows wm+mf*16+(lane&15), cols ks*16+(lane>>4)*8
            const uint32_t aoff = ks * 32 + (lane >> 4) * 16;   // bytes
#pragma unroll
            for (int mf = 0; mf < 4; mf++) {
                uint32_t addr = aBase + (wm + mf * 16 + (lane & 15)) * 80 + aoff;
                ldsm_x4(af[mf], addr);
            }
            // B frags: rows wn+nf*8+(lane&7), cols ks*16+((lane>>3)&1)*8
            const uint32_t boff = ks * 32 + ((lane >> 3) & 1) * 16;
#pragma unroll
            for (int nf = 0; nf < 4; nf++) {
                uint32_t addr = bBase + (wn + nf * 8 + (lane & 7)) * 80 + boff;
                ldsm_x2(bf[nf], addr);
            }
#pragma unroll
            for (int mf = 0; mf < 4; mf++)
#pragma unroll
                for (int nf = 0; nf < 4; nf++)
                    mma_bf16(acc[mf][nf], af[mf], bf[nf]);
        }
        __syncthreads();
    }

    // ---- epilogue: c0,c1 -> (row lane/4, col 2*(lane%4)); c2,c3 -> row+8
    const int cm = lane >> 2, cn = (lane & 3) * 2;
#pragma unroll
    for (int mf = 0; mf < 4; mf++) {
        int e0 = bm + wm + mf * 16 + cm;
        int e1 = e0 + 8;
#pragma unroll
        for (int nf = 0; nf < 4; nf++) {
            int col = bn + wn + nf * 8 + cn;
            if (e0 < TS1)
                *reinterpret_cast<float2*>(g_preact + (size_t)e0 * NP + col) =
                    make_float2(acc[mf][nf][0], acc[mf][nf][1]);
            if (e1 < TS1)
                *reinterpret_cast<float2*>(g_preact + (size_t)e1 * NP + col) =
                    make_float2(acc[mf][nf][2], acc[mf][nf][3]);
        }
    }
}

// ---------------------------------------------------------------------------
// Kernel 2: bias + activations -> per-embedding table
// ---------------------------------------------------------------------------
__device__ __forceinline__ float sigmoidf_(float x) {
    return 1.f / (1.f + expf(-x));
}

__global__ __launch_bounds__(256)
void act_kernel(const float* __restrict__ brec) {
    int idx = blockIdx.x * blockDim.x + threadIdx.x;
    if (idx >= TS1 * HID) return;
    int e = idx / HID;
    int h = idx - e * HID;
    const float* P = g_preact + (size_t)e * NP;

    float gi  = P[0 * HID + h] + brec[0 * HID + h];
    float gz  = P[1 * HID + h] + brec[2 * HID + h];
    float go  = P[2 * HID + h] + brec[3 * HID + h];
    float gib = P[3 * HID + h] + brec[4 * HID + h];
    float gd  = P[4 * HID + h] + brec[6 * HID + h];

    float tz  = tanhf(gz);
    float cc  = sigmoidf_(gi)  * tz;
    float cb  = sigmoidf_(gib) * tz;
    float goa = sigmoidf_(go);
    float gda = fmaxf(gd, 0.f) + log1pf(expf(-fabsf(gd)));  // stable softplus

    float* T = g_table + (size_t)e * (4 * HID);
    T[0 * HID + h] = cc;
    T[1 * HID + h] = cb;
    T[2 * HID + h] = goa;
    T[3 * HID + h] = gda;
}

// ---------------------------------------------------------------------------
// Kernel 3: per-token gather + decay + write 5 outputs [5, T, B, H]
// ---------------------------------------------------------------------------
__global__ __launch_bounds__(256)
void token_kernel(const int* __restrict__ ev, const float* __restrict__ dur,
                  float* __restrict__ out) {
    const int tok = blockIdx.x;        // = t*BATCH + b (matches output layout)
    const int t = tok >> 5;
    const int b = tok & 31;

    const int   e = ev[b * SEQ + t];   // inputs are [B, T]
    const float d = dur[b * SEQ + t];

    const float* T = g_table + (size_t)e * (4 * HID);
    const int h = threadIdx.x * 4;

    float4 c  = *reinterpret_cast<const float4*>(T + 0 * HID + h);
    float4 cb = *reinterpret_cast<const float4*>(T + 1 * HID + h);
    float4 go = *reinterpret_cast<const float4*>(T + 2 * HID + h);
    float4 gd = *reinterpret_cast<const float4*>(T + 3 * HID + h);

    float4 hd;
    hd.x = go.x * tanhf(cb.x + (c.x - cb.x) * expf(-gd.x * d));
    hd.y = go.y * tanhf(cb.y + (c.y - cb.y) * expf(-gd.y * d));
    hd.z = go.z * tanhf(cb.z + (c.z - cb.z) * expf(-gd.z * d));
    hd.w = go.w * tanhf(cb.w + (c.w - cb.w) * expf(-gd.w * d));

    const size_t stride = (size_t)SEQ * BATCH * HID;
    const size_t base   = (size_t)tok * HID + h;

    *reinterpret_cast<float4*>(out + 0 * stride + base) = hd;
    *reinterpret_cast<float4*>(out + 1 * stride + base) = c;
    *reinterpret_cast<float4*>(out + 2 * stride + base) = cb;
    *reinterpret_cast<float4*>(out + 3 * stride + base) = go;
    *reinterpret_cast<float4*>(out + 4 * stride + base) = gd;
}

// ---------------------------------------------------------------------------
extern "C" void kernel_launch(void* const* d_in, const int* in_sizes, int n_in,
                              void* d_out, int out_size) {
    const int*   ev  = (const int*)  d_in[0];   // event_seqs   [32, 512] int32
    const float* dur = (const float*)d_in[1];   // duration_seqs[32, 512]
    const float* emb = (const float*)d_in[2];   // emb_table [1001, 1024]
    const float* W   = (const float*)d_in[3];   // W_rec [7168, 2048]
    const float* br  = (const float*)d_in[4];   // b_rec [7168]
    float* out = (float*)d_out;                 // [5, 512, 32, 1024]

    conv_A<<<(MPAD * HID + 255) / 256, 256>>>(emb);
    conv_B<<<(NP * HID + 255) / 256, 256>>>(W);

    dim3 g1(NP / 128, MPAD / 128);              // (40, 8)
    gemm_hmma<<<g1, 256>>>();

    act_kernel<<<(TS1 * HID + 255) / 256, 256>>>(br);

    token_kernel<<<NTOK, 256>>>(ev, dur, out);
}

// round 4
// speedup vs baseline: 1.8376x; 1.0280x over previous
#include <cuda_runtime.h>
#include <cuda_bf16.h>
#include <cstdint>

#define HID   1024
#define TS1   1001            // TYPE_SIZE + 1 embedding rows
#define MPAD  1024            // padded M (8 tiles of 128)
#define BATCH 32
#define SEQ   512
#define NTOK  (BATCH * SEQ)
#define NG    5               // used gates: gi, gz, go, gib, gd
#define NP    (NG * HID)      // 5120
#define WROW  2048            // W_rec row stride (2H)
#define KK    3072            // K' = 3 * HID  (hi*hi | lo*hi | hi*lo)

// ---------------- device-global scratch (no allocs allowed) ----------------
__device__ __nv_bfloat16 g_A[MPAD * KK];     // 6 MB   A' = [hi | lo | hi]
__device__ __nv_bfloat16 g_B[NP * KK];       // 30 MB  B' = [hi | hi | lo]
__device__ float g_preact[TS1 * NP];         // 20.5 MB
__device__ float g_table [TS1 * 4 * HID];    // 16.4 MB

__constant__ int c_chunk[NG] = {0, 2, 3, 4, 6};   // gi, gz, go, gib, gd

// ---------------- base-target PTX helpers ----------------
__device__ __forceinline__ uint32_t smem_u32(const void* p) {
    uint32_t a;
    asm("{ .reg .u64 t; cvta.to.shared.u64 t, %1; cvt.u32.u64 %0, t; }"
        : "=r"(a) : "l"(p));
    return a;
}
#define CP_ASYNC16(dst, src) \
    asm volatile("cp.async.cg.shared.global [%0], [%1], 16;" \
                 :: "r"(dst), "l"(src))
#define CP_COMMIT() asm volatile("cp.async.commit_group;" ::: "memory")
#define CP_WAIT0()  asm volatile("cp.async.wait_group 0;" ::: "memory")
#define CP_WAIT1()  asm volatile("cp.async.wait_group 1;" ::: "memory")

__device__ __forceinline__ void ldsm_x4(uint32_t* r, uint32_t addr) {
    asm volatile("ldmatrix.sync.aligned.m8n8.x4.shared.b16 {%0,%1,%2,%3}, [%4];"
        : "=r"(r[0]), "=r"(r[1]), "=r"(r[2]), "=r"(r[3]) : "r"(addr));
}
__device__ __forceinline__ void ldsm_x2(uint32_t* r, uint32_t addr) {
    asm volatile("ldmatrix.sync.aligned.m8n8.x2.shared.b16 {%0,%1}, [%2];"
        : "=r"(r[0]), "=r"(r[1]) : "r"(addr));
}
__device__ __forceinline__ void mma_bf16(float* c, const uint32_t* a,
                                         const uint32_t* b) {
    asm volatile(
        "mma.sync.aligned.m16n8k16.row.col.f32.bf16.bf16.f32 "
        "{%0,%1,%2,%3}, {%4,%5,%6,%7}, {%8,%9}, {%0,%1,%2,%3};"
        : "+f"(c[0]), "+f"(c[1]), "+f"(c[2]), "+f"(c[3])
        : "r"(a[0]), "r"(a[1]), "r"(a[2]), "r"(a[3]), "r"(b[0]), "r"(b[1]));
}

// ---- fast-but-accurate transcendentals (MUFU: ~2^-22 rel err) ----
#define LOG2E 1.4426950408889634f
#define LN2   0.6931471805599453f
__device__ __forceinline__ float ex2f(float x) {
    float y; asm("ex2.approx.f32 %0, %1;" : "=f"(y) : "f"(x)); return y;
}
__device__ __forceinline__ float lg2f(float x) {
    float y; asm("lg2.approx.f32 %0, %1;" : "=f"(y) : "f"(x)); return y;
}
__device__ __forceinline__ float rcpf(float x) {
    float y; asm("rcp.approx.f32 %0, %1;" : "=f"(y) : "f"(x)); return y;
}
__device__ __forceinline__ float fexpf(float x)   { return ex2f(x * LOG2E); }
__device__ __forceinline__ float fsigmoid(float x){ return rcpf(1.f + ex2f(-x * LOG2E)); }
// stable softplus: max(x,0) + log(1 + e^{-|x|})
__device__ __forceinline__ float fsoftplus(float x) {
    float e = ex2f(-fabsf(x) * LOG2E);
    return fmaxf(x, 0.f) + LN2 * lg2f(1.f + e);
}

// ---------------------------------------------------------------------------
// Kernel 0a/0b: fp32 -> bf16 hi/lo split, packed along K'
// ---------------------------------------------------------------------------
__global__ __launch_bounds__(256)
void conv_A(const float* __restrict__ emb) {
    int idx = blockIdx.x * 256 + threadIdx.x;       // over MPAD*HID
    if (idx >= MPAD * HID) return;
    int e = idx >> 10, k = idx & 1023;
    float a = (e < TS1) ? emb[idx] : 0.f;
    __nv_bfloat16 hi = __float2bfloat16(a);
    __nv_bfloat16 lo = __float2bfloat16(a - __bfloat162float(hi));
    __nv_bfloat16* dst = g_A + (size_t)e * KK + k;
    dst[0]    = hi;
    dst[1024] = lo;
    dst[2048] = hi;
}

__global__ __launch_bounds__(256)
void conv_B(const float* __restrict__ W) {
    int idx = blockIdx.x * 256 + threadIdx.x;       // over NP*HID
    if (idx >= NP * HID) return;
    int n = idx >> 10, k = idx & 1023;
    int c = n >> 10, h = n & 1023;
    float a = W[(size_t)(c_chunk[c] * HID + h) * WROW + k];
    __nv_bfloat16 hi = __float2bfloat16(a);
    __nv_bfloat16 lo = __float2bfloat16(a - __bfloat162float(hi));
    __nv_bfloat16* dst = g_B + (size_t)n * KK + k;
    dst[0]    = hi;
    dst[1024] = hi;
    dst[2048] = lo;
}

// ---------------------------------------------------------------------------
// Kernel 1: bf16 mma.sync GEMM.  preact[e,n] = sum_k' A'[e,k'] * B'[n,k']
// 128x128 block, BK=32, THREE-stage cp.async pipeline, ONE barrier per iter.
// SMEM row stride 40 bf16 (80 B): conflict-free LDSM.
// ---------------------------------------------------------------------------
#define BK      32
#define LDS_S   40                        // smem row stride (bf16 elems)
#define KT      (KK / BK)                 // 96
#define MAT_B   (128 * LDS_S * 2)         // 10240 bytes per matrix per stage
#define STG_B   (2 * MAT_B)               // 20480 bytes per stage
#define SMEM_SZ (3 * STG_B)               // 61440 bytes

__global__ __launch_bounds__(256, 2)
void gemm_hmma() {
    extern __shared__ __align__(16) char smem[];
    const uint32_t sbase = smem_u32(smem);

    const int tid = threadIdx.x;
    const int wid = tid >> 5, lane = tid & 31;
    const int bm = blockIdx.y * 128;
    const int bn = blockIdx.x * 128;
    const int wm = (wid >> 2) * 64;        // warp m offset (0 | 64)
    const int wn = (wid & 3) * 32;         // warp n offset (0..96)

    const __nv_bfloat16* gA = g_A + (size_t)bm * KK;
    const __nv_bfloat16* gB = g_B + (size_t)bn * KK;

    // per-thread load slots: 2 chunks of 16B per matrix per stage
    const int r0 = tid >> 2, g0 = tid & 3;
    const int r1 = (tid + 256) >> 2;

    auto issue = [&](int kt, int s) {
        const int k0 = kt * BK;
        const uint32_t dA = sbase + s * STG_B;
        const uint32_t dB = dA + MAT_B;
        CP_ASYNC16(dA + r0 * 80 + g0 * 16, gA + (size_t)r0 * KK + k0 + g0 * 8);
        CP_ASYNC16(dA + r1 * 80 + g0 * 16, gA + (size_t)r1 * KK + k0 + g0 * 8);
        CP_ASYNC16(dB + r0 * 80 + g0 * 16, gB + (size_t)r0 * KK + k0 + g0 * 8);
        CP_ASYNC16(dB + r1 * 80 + g0 * 16, gB + (size_t)r1 * KK + k0 + g0 * 8);
    };

    float acc[4][4][4];
#pragma unroll
    for (int i = 0; i < 4; i++)
#pragma unroll
        for (int j = 0; j < 4; j++)
#pragma unroll
            for (int v = 0; v < 4; v++) acc[i][j][v] = 0.f;

    issue(0, 0); CP_COMMIT();
    issue(1, 1); CP_COMMIT();

    int s = 0;
    for (int kt = 0; kt < KT; kt++) {
        if (kt < KT - 1) CP_WAIT1(); else CP_WAIT0();
        __syncthreads();

        const uint32_t aBase = sbase + s * STG_B;
        const uint32_t bBase = aBase + MAT_B;

        uint32_t af[4][4], bf[4][2];
        // ---- ks = 0 fragments
        {
            const uint32_t aoff = (lane >> 4) * 16;
#pragma unroll
            for (int mf = 0; mf < 4; mf++)
                ldsm_x4(af[mf], aBase + (wm + mf * 16 + (lane & 15)) * 80 + aoff);
            const uint32_t boff = ((lane >> 3) & 1) * 16;
#pragma unroll
            for (int nf = 0; nf < 4; nf++)
                ldsm_x2(bf[nf], bBase + (wn + nf * 8 + (lane & 7)) * 80 + boff);
        }
        // prefetch kt+2 into the stage consumed at kt-1 (safe: barrier above)
        if (kt + 2 < KT) {
            int s2 = s + 2; if (s2 >= 3) s2 -= 3;
            issue(kt + 2, s2);
            CP_COMMIT();
        }
#pragma unroll
        for (int mf = 0; mf < 4; mf++)
#pragma unroll
            for (int nf = 0; nf < 4; nf++)
                mma_bf16(acc[mf][nf], af[mf], bf[nf]);

        // ---- ks = 1 fragments
        {
            const uint32_t aoff = 32 + (lane >> 4) * 16;
#pragma unroll
            for (int mf = 0; mf < 4; mf++)
                ldsm_x4(af[mf], aBase + (wm + mf * 16 + (lane & 15)) * 80 + aoff);
            const uint32_t boff = 32 + ((lane >> 3) & 1) * 16;
#pragma unroll
            for (int nf = 0; nf < 4; nf++)
                ldsm_x2(bf[nf], bBase + (wn + nf * 8 + (lane & 7)) * 80 + boff);
        }
#pragma unroll
        for (int mf = 0; mf < 4; mf++)
#pragma unroll
            for (int nf = 0; nf < 4; nf++)
                mma_bf16(acc[mf][nf], af[mf], bf[nf]);

        if (++s == 3) s = 0;
    }

    // ---- epilogue
    const int cm = lane >> 2, cn = (lane & 3) * 2;
#pragma unroll
    for (int mf = 0; mf < 4; mf++) {
        int e0 = bm + wm + mf * 16 + cm;
        int e1 = e0 + 8;
#pragma unroll
        for (int nf = 0; nf < 4; nf++) {
            int col = bn + wn + nf * 8 + cn;
            if (e0 < TS1)
                *reinterpret_cast<float2*>(g_preact + (size_t)e0 * NP + col) =
                    make_float2(acc[mf][nf][0], acc[mf][nf][1]);
            if (e1 < TS1)
                *reinterpret_cast<float2*>(g_preact + (size_t)e1 * NP + col) =
                    make_float2(acc[mf][nf][2], acc[mf][nf][3]);
        }
    }
}

// ---------------------------------------------------------------------------
// Kernel 2: bias + activations -> per-embedding table
// ---------------------------------------------------------------------------
__global__ __launch_bounds__(256)
void act_kernel(const float* __restrict__ brec) {
    int idx = blockIdx.x * blockDim.x + threadIdx.x;
    if (idx >= TS1 * HID) return;
    int e = idx / HID;
    int h = idx - e * HID;
    const float* P = g_preact + (size_t)e * NP;

    float gi  = P[0 * HID + h] + brec[0 * HID + h];
    float gz  = P[1 * HID + h] + brec[2 * HID + h];
    float go  = P[2 * HID + h] + brec[3 * HID + h];
    float gib = P[3 * HID + h] + brec[4 * HID + h];
    float gd  = P[4 * HID + h] + brec[6 * HID + h];

    float tz  = tanhf(gz);                   // exact: feeds outputs directly
    float cc  = fsigmoid(gi)  * tz;
    float cb  = fsigmoid(gib) * tz;
    float goa = fsigmoid(go);
    float gda = fsoftplus(gd);

    float* T = g_table + (size_t)e * (4 * HID);
    T[0 * HID + h] = cc;
    T[1 * HID + h] = cb;
    T[2 * HID + h] = goa;
    T[3 * HID + h] = gda;
}

// ---------------------------------------------------------------------------
// Kernel 3: per-token gather + decay + write 5 outputs [5, T, B, H]
// ---------------------------------------------------------------------------
__global__ __launch_bounds__(256)
void token_kernel(const int* __restrict__ ev, const float* __restrict__ dur,
                  float* __restrict__ out) {
    const int tok = blockIdx.x;        // = t*BATCH + b (matches output layout)
    const int t = tok >> 5;
    const int b = tok & 31;

    const int   e = ev[b * SEQ + t];   // inputs are [B, T]
    const float d = dur[b * SEQ + t];
    const float dl = -d * LOG2E;       // exp(-gd*d) = ex2(gd * dl)

    const float* T = g_table + (size_t)e * (4 * HID);
    const int h = threadIdx.x * 4;

    float4 c  = *reinterpret_cast<const float4*>(T + 0 * HID + h);
    float4 cb = *reinterpret_cast<const float4*>(T + 1 * HID + h);
    float4 go = *reinterpret_cast<const float4*>(T + 2 * HID + h);
    float4 gd = *reinterpret_cast<const float4*>(T + 3 * HID + h);

    float4 hd;
    hd.x = go.x * tanhf(cb.x + (c.x - cb.x) * ex2f(gd.x * dl));
    hd.y = go.y * tanhf(cb.y + (c.y - cb.y) * ex2f(gd.y * dl));
    hd.z = go.z * tanhf(cb.z + (c.z - cb.z) * ex2f(gd.z * dl));
    hd.w = go.w * tanhf(cb.w + (c.w - cb.w) * ex2f(gd.w * dl));

    const size_t stride = (size_t)SEQ * BATCH * HID;
    const size_t base   = (size_t)tok * HID + h;

    *reinterpret_cast<float4*>(out + 0 * stride + base) = hd;
    *reinterpret_cast<float4*>(out + 1 * stride + base) = c;
    *reinterpret_cast<float4*>(out + 2 * stride + base) = cb;
    *reinterpret_cast<float4*>(out + 3 * stride + base) = go;
    *reinterpret_cast<float4*>(out + 4 * stride + base) = gd;
}

// ---------------------------------------------------------------------------
extern "C" void kernel_launch(void* const* d_in, const int* in_sizes, int n_in,
                              void* d_out, int out_size) {
    const int*   ev  = (const int*)  d_in[0];   // event_seqs   [32, 512] int32
    const float* dur = (const float*)d_in[1];   // duration_seqs[32, 512]
    const float* emb = (const float*)d_in[2];   // emb_table [1001, 1024]
    const float* W   = (const float*)d_in[3];   // W_rec [7168, 2048]
    const float* br  = (const float*)d_in[4];   // b_rec [7168]
    float* out = (float*)d_out;                 // [5, 512, 32, 1024]

    static bool attr_done = false;
    if (!attr_done) {
        cudaFuncSetAttribute(gemm_hmma,
                             cudaFuncAttributeMaxDynamicSharedMemorySize,
                             SMEM_SZ);
        attr_done = true;
    }

    conv_A<<<(MPAD * HID + 255) / 256, 256>>>(emb);
    conv_B<<<(NP * HID + 255) / 256, 256>>>(W);

    dim3 g1(NP / 128, MPAD / 128);              // (40, 8)
    gemm_hmma<<<g1, 256, SMEM_SZ>>>();

    act_kernel<<<(TS1 * HID + 255) / 256, 256>>>(br);

    token_kernel<<<NTOK, 256>>>(ev, dur, out);
}

// round 5
// speedup vs baseline: 3.0348x; 1.6515x over previous
#include <cuda_runtime.h>
#include <cuda_fp16.h>
#include <cstdint>

#define HID   1024
#define TS1   1001            // TYPE_SIZE + 1 embedding rows
#define MPAD  1024            // padded M (8 tiles of 128)
#define BATCH 32
#define SEQ   512
#define NTOK  (BATCH * SEQ)
#define NG    5               // used gates: gi, gz, go, gib, gd
#define NP    (NG * HID)      // 5120
#define WROW  2048            // W_rec row stride (2H)
#define KK    1024            // K (single-pass fp16)

// ---------------- device-global scratch (no allocs allowed) ----------------
__device__ __half g_A[MPAD * KK];            // 2 MB
__device__ __half g_B[NP * KK];              // 10 MB
__device__ float g_preact[TS1 * NP];         // 20.5 MB
__device__ float g_table [TS1 * 4 * HID];    // 16.4 MB

__constant__ int c_chunk[NG] = {0, 2, 3, 4, 6};   // gi, gz, go, gib, gd

// ---------------- base-target PTX helpers ----------------
__device__ __forceinline__ uint32_t smem_u32(const void* p) {
    uint32_t a;
    asm("{ .reg .u64 t; cvta.to.shared.u64 t, %1; cvt.u32.u64 %0, t; }"
        : "=r"(a) : "l"(p));
    return a;
}
#define CP_ASYNC16(dst, src) \
    asm volatile("cp.async.cg.shared.global [%0], [%1], 16;" \
                 :: "r"(dst), "l"(src))
#define CP_COMMIT() asm volatile("cp.async.commit_group;" ::: "memory")
#define CP_WAIT0()  asm volatile("cp.async.wait_group 0;" ::: "memory")
#define CP_WAIT1()  asm volatile("cp.async.wait_group 1;" ::: "memory")

__device__ __forceinline__ void ldsm_x4(uint32_t* r, uint32_t addr) {
    asm volatile("ldmatrix.sync.aligned.m8n8.x4.shared.b16 {%0,%1,%2,%3}, [%4];"
        : "=r"(r[0]), "=r"(r[1]), "=r"(r[2]), "=r"(r[3]) : "r"(addr));
}
__device__ __forceinline__ void ldsm_x2(uint32_t* r, uint32_t addr) {
    asm volatile("ldmatrix.sync.aligned.m8n8.x2.shared.b16 {%0,%1}, [%2];"
        : "=r"(r[0]), "=r"(r[1]) : "r"(addr));
}
__device__ __forceinline__ void mma_f16(float* c, const uint32_t* a,
                                        const uint32_t* b) {
    asm volatile(
        "mma.sync.aligned.m16n8k16.row.col.f32.f16.f16.f32 "
        "{%0,%1,%2,%3}, {%4,%5,%6,%7}, {%8,%9}, {%0,%1,%2,%3};"
        : "+f"(c[0]), "+f"(c[1]), "+f"(c[2]), "+f"(c[3])
        : "r"(a[0]), "r"(a[1]), "r"(a[2]), "r"(a[3]), "r"(b[0]), "r"(b[1]));
}

// ---- fast transcendentals (MUFU: ~2^-22 rel err) ----
#define LOG2E 1.4426950408889634f
#define LN2   0.6931471805599453f
__device__ __forceinline__ float ex2f(float x) {
    float y; asm("ex2.approx.f32 %0, %1;" : "=f"(y) : "f"(x)); return y;
}
__device__ __forceinline__ float lg2f(float x) {
    float y; asm("lg2.approx.f32 %0, %1;" : "=f"(y) : "f"(x)); return y;
}
__device__ __forceinline__ float rcpf(float x) {
    float y; asm("rcp.approx.f32 %0, %1;" : "=f"(y) : "f"(x)); return y;
}
__device__ __forceinline__ float fsigmoid(float x){ return rcpf(1.f + ex2f(-x * LOG2E)); }
__device__ __forceinline__ float fsoftplus(float x) {
    float e = ex2f(-fabsf(x) * LOG2E);
    return fmaxf(x, 0.f) + LN2 * lg2f(1.f + e);
}

// ---------------------------------------------------------------------------
// Kernel 0a/0b: fp32 -> fp16 conversion (gather used W rows for B)
// ---------------------------------------------------------------------------
__global__ __launch_bounds__(256)
void conv_A(const float* __restrict__ emb) {
    int idx = blockIdx.x * 256 + threadIdx.x;       // over MPAD*HID
    if (idx >= MPAD * HID) return;
    int e = idx >> 10;
    float a = (e < TS1) ? emb[idx] : 0.f;
    g_A[idx] = __float2half_rn(a);
}

__global__ __launch_bounds__(256)
void conv_B(const float* __restrict__ W) {
    int idx = blockIdx.x * 256 + threadIdx.x;       // over NP*HID
    if (idx >= NP * HID) return;
    int n = idx >> 10, k = idx & 1023;
    int c = n >> 10, h = n & 1023;
    float a = W[(size_t)(c_chunk[c] * HID + h) * WROW + k];
    g_B[idx] = __float2half_rn(a);
}

// ---------------------------------------------------------------------------
// Kernel 1: fp16 mma.sync GEMM.  preact[e,n] = sum_k A[e,k] * B[n,k]
// 128x128 block, BK=32 (64 B/row/iter), 3-stage cp.async, 1 barrier/iter.
// SMEM row stride 80 B: conflict-free LDSM.
// ---------------------------------------------------------------------------
#define BK      32
#define KT      (KK / BK)                 // 32
#define MAT_B   (128 * 80)                // 10240 bytes per matrix per stage
#define STG_B   (2 * MAT_B)               // 20480 bytes per stage
#define SMEM_SZ (3 * STG_B)               // 61440 bytes

__global__ __launch_bounds__(256, 2)
void gemm_hmma() {
    extern __shared__ __align__(16) char smem[];
    const uint32_t sbase = smem_u32(smem);

    const int tid = threadIdx.x;
    const int wid = tid >> 5, lane = tid & 31;
    const int bm = blockIdx.y * 128;
    const int bn = blockIdx.x * 128;
    const int wm = (wid >> 2) * 64;        // warp m offset (0 | 64)
    const int wn = (wid & 3) * 32;         // warp n offset (0..96)

    const __half* gA = g_A + (size_t)bm * KK;
    const __half* gB = g_B + (size_t)bn * KK;

    const int r0 = tid >> 2, g0 = tid & 3;
    const int r1 = (tid + 256) >> 2;

    auto issue = [&](int kt, int s) {
        const int k0 = kt * BK;
        const uint32_t dA = sbase + s * STG_B;
        const uint32_t dB = dA + MAT_B;
        CP_ASYNC16(dA + r0 * 80 + g0 * 16, gA + (size_t)r0 * KK + k0 + g0 * 8);
        CP_ASYNC16(dA + r1 * 80 + g0 * 16, gA + (size_t)r1 * KK + k0 + g0 * 8);
        CP_ASYNC16(dB + r0 * 80 + g0 * 16, gB + (size_t)r0 * KK + k0 + g0 * 8);
        CP_ASYNC16(dB + r1 * 80 + g0 * 16, gB + (size_t)r1 * KK + k0 + g0 * 8);
    };

    float acc[4][4][4];
#pragma unroll
    for (int i = 0; i < 4; i++)
#pragma unroll
        for (int j = 0; j < 4; j++)
#pragma unroll
            for (int v = 0; v < 4; v++) acc[i][j][v] = 0.f;

    issue(0, 0); CP_COMMIT();
    issue(1, 1); CP_COMMIT();

    int s = 0;
    for (int kt = 0; kt < KT; kt++) {
        if (kt < KT - 1) CP_WAIT1(); else CP_WAIT0();
        __syncthreads();

        const uint32_t aBase = sbase + s * STG_B;
        const uint32_t bBase = aBase + MAT_B;

        uint32_t af[4][4], bf[4][2];
        // ---- ks = 0 fragments
        {
            const uint32_t aoff = (lane >> 4) * 16;
#pragma unroll
            for (int mf = 0; mf < 4; mf++)
                ldsm_x4(af[mf], aBase + (wm + mf * 16 + (lane & 15)) * 80 + aoff);
            const uint32_t boff = ((lane >> 3) & 1) * 16;
#pragma unroll
            for (int nf = 0; nf < 4; nf++)
                ldsm_x2(bf[nf], bBase + (wn + nf * 8 + (lane & 7)) * 80 + boff);
        }
        // prefetch kt+2 into the stage consumed at kt-1
        if (kt + 2 < KT) {
            int s2 = s + 2; if (s2 >= 3) s2 -= 3;
            issue(kt + 2, s2);
            CP_COMMIT();
        }
#pragma unroll
        for (int mf = 0; mf < 4; mf++)
#pragma unroll
            for (int nf = 0; nf < 4; nf++)
                mma_f16(acc[mf][nf], af[mf], bf[nf]);

        // ---- ks = 1 fragments
        {
            const uint32_t aoff = 32 + (lane >> 4) * 16;
#pragma unroll
            for (int mf = 0; mf < 4; mf++)
                ldsm_x4(af[mf], aBase + (wm + mf * 16 + (lane & 15)) * 80 + aoff);
            const uint32_t boff = 32 + ((lane >> 3) & 1) * 16;
#pragma unroll
            for (int nf = 0; nf < 4; nf++)
                ldsm_x2(bf[nf], bBase + (wn + nf * 8 + (lane & 7)) * 80 + boff);
        }
#pragma unroll
        for (int mf = 0; mf < 4; mf++)
#pragma unroll
            for (int nf = 0; nf < 4; nf++)
                mma_f16(acc[mf][nf], af[mf], bf[nf]);

        if (++s == 3) s = 0;
    }

    // ---- epilogue
    const int cm = lane >> 2, cn = (lane & 3) * 2;
#pragma unroll
    for (int mf = 0; mf < 4; mf++) {
        int e0 = bm + wm + mf * 16 + cm;
        int e1 = e0 + 8;
#pragma unroll
        for (int nf = 0; nf < 4; nf++) {
            int col = bn + wn + nf * 8 + cn;
            if (e0 < TS1)
                *reinterpret_cast<float2*>(g_preact + (size_t)e0 * NP + col) =
                    make_float2(acc[mf][nf][0], acc[mf][nf][1]);
            if (e1 < TS1)
                *reinterpret_cast<float2*>(g_preact + (size_t)e1 * NP + col) =
                    make_float2(acc[mf][nf][2], acc[mf][nf][3]);
        }
    }
}

// ---------------------------------------------------------------------------
// Kernel 2: bias + activations -> per-embedding table
// ---------------------------------------------------------------------------
__global__ __launch_bounds__(256)
void act_kernel(const float* __restrict__ brec) {
    int idx = blockIdx.x * blockDim.x + threadIdx.x;
    if (idx >= TS1 * HID) return;
    int e = idx / HID;
    int h = idx - e * HID;
    const float* P = g_preact + (size_t)e * NP;

    float gi  = P[0 * HID + h] + brec[0 * HID + h];
    float gz  = P[1 * HID + h] + brec[2 * HID + h];
    float go  = P[2 * HID + h] + brec[3 * HID + h];
    float gib = P[3 * HID + h] + brec[4 * HID + h];
    float gd  = P[4 * HID + h] + brec[6 * HID + h];

    float tz  = tanhf(gz);                   // exact: feeds outputs directly
    float cc  = fsigmoid(gi)  * tz;
    float cb  = fsigmoid(gib) * tz;
    float goa = fsigmoid(go);
    float gda = fsoftplus(gd);

    float* T = g_table + (size_t)e * (4 * HID);
    T[0 * HID + h] = cc;
    T[1 * HID + h] = cb;
    T[2 * HID + h] = goa;
    T[3 * HID + h] = gda;
}

// ---------------------------------------------------------------------------
// Kernel 3: per-token gather + decay + write 5 outputs [5, T, B, H]
// ---------------------------------------------------------------------------
__global__ __launch_bounds__(256)
void token_kernel(const int* __restrict__ ev, const float* __restrict__ dur,
                  float* __restrict__ out) {
    const int tok = blockIdx.x;        // = t*BATCH + b (matches output layout)
    const int t = tok >> 5;
    const int b = tok & 31;

    const int   e = ev[b * SEQ + t];   // inputs are [B, T]
    const float d = dur[b * SEQ + t];
    const float dl = -d * LOG2E;       // exp(-gd*d) = ex2(gd * dl)

    const float* T = g_table + (size_t)e * (4 * HID);
    const int h = threadIdx.x * 4;

    float4 c  = *reinterpret_cast<const float4*>(T + 0 * HID + h);
    float4 cb = *reinterpret_cast<const float4*>(T + 1 * HID + h);
    float4 go = *reinterpret_cast<const float4*>(T + 2 * HID + h);
    float4 gd = *reinterpret_cast<const float4*>(T + 3 * HID + h);

    float4 hd;
    hd.x = go.x * tanhf(cb.x + (c.x - cb.x) * ex2f(gd.x * dl));
    hd.y = go.y * tanhf(cb.y + (c.y - cb.y) * ex2f(gd.y * dl));
    hd.z = go.z * tanhf(cb.z + (c.z - cb.z) * ex2f(gd.z * dl));
    hd.w = go.w * tanhf(cb.w + (c.w - cb.w) * ex2f(gd.w * dl));

    const size_t stride = (size_t)SEQ * BATCH * HID;
    const size_t base   = (size_t)tok * HID + h;

    *reinterpret_cast<float4*>(out + 0 * stride + base) = hd;
    *reinterpret_cast<float4*>(out + 1 * stride + base) = c;
    *reinterpret_cast<float4*>(out + 2 * stride + base) = cb;
    *reinterpret_cast<float4*>(out + 3 * stride + base) = go;
    *reinterpret_cast<float4*>(out + 4 * stride + base) = gd;
}

// ---------------------------------------------------------------------------
extern "C" void kernel_launch(void* const* d_in, const int* in_sizes, int n_in,
                              void* d_out, int out_size) {
    const int*   ev  = (const int*)  d_in[0];   // event_seqs   [32, 512] int32
    const float* dur = (const float*)d_in[1];   // duration_seqs[32, 512]
    const float* emb = (const float*)d_in[2];   // emb_table [1001, 1024]
    const float* W   = (const float*)d_in[3];   // W_rec [7168, 2048]
    const float* br  = (const float*)d_in[4];   // b_rec [7168]
    float* out = (float*)d_out;                 // [5, 512, 32, 1024]

    static bool attr_done = false;
    if (!attr_done) {
        cudaFuncSetAttribute(gemm_hmma,
                             cudaFuncAttributeMaxDynamicSharedMemorySize,
                             SMEM_SZ);
        attr_done = true;
    }

    conv_A<<<(MPAD * HID + 255) / 256, 256>>>(emb);
    conv_B<<<(NP * HID + 255) / 256, 256>>>(W);

    dim3 g1(NP / 128, MPAD / 128);              // (40, 8)
    gemm_hmma<<<g1, 256, SMEM_SZ>>>();

    act_kernel<<<(TS1 * HID + 255) / 256, 256>>>(br);

    token_kernel<<<NTOK, 256>>>(ev, dur, out);
}

// round 6
// speedup vs baseline: 3.6012x; 1.1866x over previous
#include <cuda_runtime.h>
#include <cuda_fp16.h>
#include <cstdint>

#define HID   1024
#define TS1   1001            // TYPE_SIZE + 1 embedding rows
#define MPAD  1024            // padded M (16 tiles of 64)
#define BATCH 32
#define SEQ   512
#define NTOK  (BATCH * SEQ)
#define NG    5               // used gates: gi, gz, go, gib, gd
#define NP    (NG * HID)      // 5120
#define WROW  2048            // W_rec row stride (2H)
#define KK    1024            // K (single-pass fp16)

// ---------------- device-global scratch (no allocs allowed) ----------------
__device__ __half g_A[MPAD * KK];            // 2 MB
__device__ __half g_B[NP * KK];              // 10 MB
__device__ float g_table[TS1 * 4 * HID];     // 16.4 MB {c, c_bar, sig(go), softplus(gd)}

__constant__ int c_chunk[NG] = {0, 2, 3, 4, 6};   // gi, gz, go, gib, gd

// ---------------- base-target PTX helpers ----------------
__device__ __forceinline__ uint32_t smem_u32(const void* p) {
    uint32_t a;
    asm("{ .reg .u64 t; cvta.to.shared.u64 t, %1; cvt.u32.u64 %0, t; }"
        : "=r"(a) : "l"(p));
    return a;
}
#define CP_ASYNC16(dst, src) \
    asm volatile("cp.async.cg.shared.global [%0], [%1], 16;" \
                 :: "r"(dst), "l"(src))
#define CP_COMMIT() asm volatile("cp.async.commit_group;" ::: "memory")
#define CP_WAIT0()  asm volatile("cp.async.wait_group 0;" ::: "memory")
#define CP_WAIT1()  asm volatile("cp.async.wait_group 1;" ::: "memory")

__device__ __forceinline__ void ldsm_x4(uint32_t* r, uint32_t addr) {
    asm volatile("ldmatrix.sync.aligned.m8n8.x4.shared.b16 {%0,%1,%2,%3}, [%4];"
        : "=r"(r[0]), "=r"(r[1]), "=r"(r[2]), "=r"(r[3]) : "r"(addr));
}
__device__ __forceinline__ void mma_f16(float* c, const uint32_t* a,
                                        uint32_t b0, uint32_t b1) {
    asm volatile(
        "mma.sync.aligned.m16n8k16.row.col.f32.f16.f16.f32 "
        "{%0,%1,%2,%3}, {%4,%5,%6,%7}, {%8,%9}, {%0,%1,%2,%3};"
        : "+f"(c[0]), "+f"(c[1]), "+f"(c[2]), "+f"(c[3])
        : "r"(a[0]), "r"(a[1]), "r"(a[2]), "r"(a[3]), "r"(b0), "r"(b1));
}

// ---- fast transcendentals (MUFU) ----
#define LOG2E 1.4426950408889634f
#define LN2   0.6931471805599453f
__device__ __forceinline__ float ex2f(float x) {
    float y; asm("ex2.approx.f32 %0, %1;" : "=f"(y) : "f"(x)); return y;
}
__device__ __forceinline__ float lg2f(float x) {
    float y; asm("lg2.approx.f32 %0, %1;" : "=f"(y) : "f"(x)); return y;
}
__device__ __forceinline__ float rcpf(float x) {
    float y; asm("rcp.approx.f32 %0, %1;" : "=f"(y) : "f"(x)); return y;
}
__device__ __forceinline__ float fsigmoid(float x){ return rcpf(1.f + ex2f(-x * LOG2E)); }
__device__ __forceinline__ float fsoftplus(float x) {
    float e = ex2f(-fabsf(x) * LOG2E);
    return fmaxf(x, 0.f) + LN2 * lg2f(1.f + e);
}

// ---------------------------------------------------------------------------
// Kernel 0a/0b: fp32 -> fp16 conversion (gather used W rows for B)
// ---------------------------------------------------------------------------
__global__ __launch_bounds__(256)
void conv_A(const float* __restrict__ emb) {
    int idx = blockIdx.x * 256 + threadIdx.x;       // over MPAD*HID
    if (idx >= MPAD * HID) return;
    int e = idx >> 10;
    float a = (e < TS1) ? emb[idx] : 0.f;
    g_A[idx] = __float2half_rn(a);
}

__global__ __launch_bounds__(256)
void conv_B(const float* __restrict__ W) {
    int idx = blockIdx.x * 256 + threadIdx.x;       // over NP*HID
    if (idx >= NP * HID) return;
    int n = idx >> 10, k = idx & 1023;
    int c = n >> 10, h = n & 1023;
    float a = W[(size_t)(c_chunk[c] * HID + h) * WROW + k];
    g_B[idx] = __float2half_rn(a);
}

// ---------------------------------------------------------------------------
// Kernel 1 (FUSED): fp16 mma.sync GEMM over ALL 5 gates + activation epilogue.
// Block tile: 64 e-rows x 64 h-cols, computing 5 gate tiles in one K-loop
// (A-fragments shared across gates). Grid 16x16 = 256 blocks -> single wave
// at 2 CTAs/SM. Epilogue applies sigmoid/tanh/softplus and writes g_table.
// 8 warps as 4(m) x 2(n): warp tile 16 x 32 per gate. acc = 5*4*4 = 80 regs.
// SMEM: 3 stages x (1 A-tile + 5 B-tiles) x 5120B = 92160 B.
// ---------------------------------------------------------------------------
#define BK      32
#define KT      (KK / BK)                 // 32
#define TILE_B  (64 * 80)                 // 5120 B per 64-row tile per stage
#define STG_B   (6 * TILE_B)              // 30720 B per stage
#define SMEM_SZ (3 * STG_B)               // 92160 B

__global__ __launch_bounds__(256, 2)
void gemm_fused(const float* __restrict__ brec) {
    extern __shared__ __align__(16) char smem[];
    const uint32_t sbase = smem_u32(smem);

    const int tid = threadIdx.x;
    const int wid = tid >> 5, lane = tid & 31;
    const int bh = blockIdx.x * 64;        // h-tile (within HID)
    const int bm = blockIdx.y * 64;        // e-tile
    const int wm = (wid >> 1) * 16;        // warp m offset: 0,16,32,48
    const int wn = (wid & 1) * 32;         // warp n offset: 0,32

    const __half* gA = g_A + (size_t)bm * KK;
    const __half* gB = g_B + (size_t)bh * KK;   // gate g row: + g*HID*KK

    const int lrow = tid >> 2, lch = tid & 3;   // load slot: row 0..63, chunk 0..3

    auto issue = [&](int kt, int s) {
        const int k0 = kt * BK;
        const uint32_t st = sbase + s * STG_B;
        const uint32_t doff = lrow * 80 + lch * 16;
        const size_t   soff = (size_t)lrow * KK + k0 + lch * 8;
        CP_ASYNC16(st + doff, gA + soff);
#pragma unroll
        for (int g = 0; g < NG; g++)
            CP_ASYNC16(st + (g + 1) * TILE_B + doff,
                       gB + (size_t)g * HID * KK + soff);
    };

    float acc[NG][4][4];
#pragma unroll
    for (int g = 0; g < NG; g++)
#pragma unroll
        for (int j = 0; j < 4; j++)
#pragma unroll
            for (int v = 0; v < 4; v++) acc[g][j][v] = 0.f;

    issue(0, 0); CP_COMMIT();
    issue(1, 1); CP_COMMIT();

    // ldmatrix lane addressing (shared by A and B x4 loads):
    const uint32_t lmoff = (lane & 15) * 80 + (lane >> 4) * 16;

    int s = 0;
    for (int kt = 0; kt < KT; kt++) {
        if (kt < KT - 1) CP_WAIT1(); else CP_WAIT0();
        __syncthreads();

        const uint32_t aBase = sbase + s * STG_B;

#pragma unroll
        for (int ks = 0; ks < 2; ks++) {
            uint32_t af[4];
            ldsm_x4(af, aBase + wm * 80 + ks * 32 + lmoff);
            if (ks == 0 && kt + 2 < KT) {       // prefetch into stage kt-1 used
                int s2 = s + 2; if (s2 >= 3) s2 -= 3;
                issue(kt + 2, s2);
                CP_COMMIT();
            }
#pragma unroll
            for (int g = 0; g < NG; g++) {
                const uint32_t bBase = aBase + (g + 1) * TILE_B + ks * 32 + lmoff;
                uint32_t b0[4], b1[4];
                ldsm_x4(b0, bBase + wn * 80);           // n 0-15 of warp tile
                ldsm_x4(b1, bBase + (wn + 16) * 80);    // n 16-31
                // x4 B layout: {r0,r2}=n0-7, {r1,r3}=n8-15
                mma_f16(acc[g][0], af, b0[0], b0[2]);
                mma_f16(acc[g][1], af, b0[1], b0[3]);
                mma_f16(acc[g][2], af, b1[0], b1[2]);
                mma_f16(acc[g][3], af, b1[1], b1[3]);
            }
        }
        if (++s == 3) s = 0;
    }

    // ---- fused activation epilogue ----
    // acc[g][nf] = {(cm,cn), (cm,cn+1), (cm+8,cn), (cm+8,cn+1)}
    const int cm = lane >> 2, cn = (lane & 3) * 2;
    const int e0 = bm + wm + cm;
    const int e1 = e0 + 8;

#pragma unroll
    for (int nf = 0; nf < 4; nf++) {
        const int col = bh + wn + nf * 8 + cn;
        const float2 bgi = *reinterpret_cast<const float2*>(brec + 0 * HID + col);
        const float2 bgz = *reinterpret_cast<const float2*>(brec + 2 * HID + col);
        const float2 bgo = *reinterpret_cast<const float2*>(brec + 3 * HID + col);
        const float2 bgb = *reinterpret_cast<const float2*>(brec + 4 * HID + col);
        const float2 bgd = *reinterpret_cast<const float2*>(brec + 6 * HID + col);
#pragma unroll
        for (int half = 0; half < 2; half++) {
            const int e = half ? e1 : e0;
            if (e >= TS1) continue;
            const int v = half * 2;
            float gi0 = acc[0][nf][v]     + bgi.x, gi1 = acc[0][nf][v + 1] + bgi.y;
            float gz0 = acc[1][nf][v]     + bgz.x, gz1 = acc[1][nf][v + 1] + bgz.y;
            float go0 = acc[2][nf][v]     + bgo.x, go1 = acc[2][nf][v + 1] + bgo.y;
            float gb0 = acc[3][nf][v]     + bgb.x, gb1 = acc[3][nf][v + 1] + bgb.y;
            float gd0 = acc[4][nf][v]     + bgd.x, gd1 = acc[4][nf][v + 1] + bgd.y;

            float tz0 = tanhf(gz0), tz1 = tanhf(gz1);
            float cc0 = fsigmoid(gi0) * tz0, cc1 = fsigmoid(gi1) * tz1;
            float cb0 = fsigmoid(gb0) * tz0, cb1 = fsigmoid(gb1) * tz1;
            float oa0 = fsigmoid(go0),       oa1 = fsigmoid(go1);
            float da0 = fsoftplus(gd0),      da1 = fsoftplus(gd1);

            float* T = g_table + (size_t)e * (4 * HID) + col;
            *reinterpret_cast<float2*>(T + 0 * HID) = make_float2(cc0, cc1);
            *reinterpret_cast<float2*>(T + 1 * HID) = make_float2(cb0, cb1);
            *reinterpret_cast<float2*>(T + 2 * HID) = make_float2(oa0, oa1);
            *reinterpret_cast<float2*>(T + 3 * HID) = make_float2(da0, da1);
        }
    }
}

// ---------------------------------------------------------------------------
// Kernel 3: per-token gather + decay + write 5 outputs [5, T, B, H]
// Streaming stores (.cs): output has zero reuse; keep L2 for the table.
// ---------------------------------------------------------------------------
__global__ __launch_bounds__(256)
void token_kernel(const int* __restrict__ ev, const float* __restrict__ dur,
                  float* __restrict__ out) {
    const int tok = blockIdx.x;        // = t*BATCH + b (matches output layout)
    const int t = tok >> 5;
    const int b = tok & 31;

    const int   e = ev[b * SEQ + t];   // inputs are [B, T]
    const float d = dur[b * SEQ + t];
    const float dl = -d * LOG2E;       // exp(-gd*d) = ex2(gd * dl)

    const float* T = g_table + (size_t)e * (4 * HID);
    const int h = threadIdx.x * 4;

    float4 c  = *reinterpret_cast<const float4*>(T + 0 * HID + h);
    float4 cb = *reinterpret_cast<const float4*>(T + 1 * HID + h);
    float4 go = *reinterpret_cast<const float4*>(T + 2 * HID + h);
    float4 gd = *reinterpret_cast<const float4*>(T + 3 * HID + h);

    float4 hd;
    hd.x = go.x * tanhf(cb.x + (c.x - cb.x) * ex2f(gd.x * dl));
    hd.y = go.y * tanhf(cb.y + (c.y - cb.y) * ex2f(gd.y * dl));
    hd.z = go.z * tanhf(cb.z + (c.z - cb.z) * ex2f(gd.z * dl));
    hd.w = go.w * tanhf(cb.w + (c.w - cb.w) * ex2f(gd.w * dl));

    const size_t stride = (size_t)SEQ * BATCH * HID;
    float* base = out + (size_t)tok * HID + h;

    __stcs(reinterpret_cast<float4*>(base + 0 * stride), hd);
    __stcs(reinterpret_cast<float4*>(base + 1 * stride), c);
    __stcs(reinterpret_cast<float4*>(base + 2 * stride), cb);
    __stcs(reinterpret_cast<float4*>(base + 3 * stride), go);
    __stcs(reinterpret_cast<float4*>(base + 4 * stride), gd);
}

// ---------------------------------------------------------------------------
extern "C" void kernel_launch(void* const* d_in, const int* in_sizes, int n_in,
                              void* d_out, int out_size) {
    const int*   ev  = (const int*)  d_in[0];   // event_seqs   [32, 512] int32
    const float* dur = (const float*)d_in[1];   // duration_seqs[32, 512]
    const float* emb = (const float*)d_in[2];   // emb_table [1001, 1024]
    const float* W   = (const float*)d_in[3];   // W_rec [7168, 2048]
    const float* br  = (const float*)d_in[4];   // b_rec [7168]
    float* out = (float*)d_out;                 // [5, 512, 32, 1024]

    static bool attr_done = false;
    if (!attr_done) {
        cudaFuncSetAttribute(gemm_fused,
                             cudaFuncAttributeMaxDynamicSharedMemorySize,
                             SMEM_SZ);
        attr_done = true;
    }

    conv_A<<<(MPAD * HID + 255) / 256, 256>>>(emb);
    conv_B<<<(NP * HID + 255) / 256, 256>>>(W);

    dim3 g1(HID / 64, MPAD / 64);               // (16, 16) = 256 blocks
    gemm_fused<<<g1, 256, SMEM_SZ>>>(br);

    token_kernel<<<NTOK, 256>>>(ev, dur, out);
}